// round 1
// baseline (speedup 1.0000x reference)
#include <cuda_runtime.h>

#define Nn 16384
#define CIN 128
#define HH 64
#define KK 64

// ---------------- device scratch (no allocations allowed) ----------------
__device__ float g_xw[Nn*HH];     // x @ W1
__device__ float g_hacc[Nn*HH];   // GCN accumulator, then relu'd h
__device__ float g_deg[Nn];       // GCN degree (incl. self loop weight 1)
__device__ float g_dis[Nn];       // rsqrt(deg)
__device__ float g_degadj[Nn];    // column sums of dense adj (edge counts)
__device__ float g_ss[KK*KK];     // s^T s
__device__ float g_ca[KK];        // s^T deg_adj
__device__ float g_cs[KK];        // column sums of s
__device__ double g_trace;        // trace(s^T adj s)

// ---------------- init: zero accumulators each replay ----------------
__global__ void k_init() {
    int i = blockIdx.x * blockDim.x + threadIdx.x;
    int stride = gridDim.x * blockDim.x;
    for (int j = i; j < Nn*HH; j += stride) g_hacc[j] = 0.f;
    for (int j = i; j < Nn;    j += stride) { g_deg[j] = 1.0f; g_degadj[j] = 0.f; }
    for (int j = i; j < KK*KK; j += stride) g_ss[j] = 0.f;
    if (i < KK) { g_ca[i] = 0.f; g_cs[i] = 0.f; }
    if (i == 0) g_trace = 0.0;
}

// ---------------- xw = x @ W1  (N,128)x(128,64) ----------------
// warp handles 4 rows; lane owns 2 output cols; W1 staged in smem.
__global__ __launch_bounds__(256) void k_xw(const float* __restrict__ x,
                                            const float* __restrict__ W1) {
    __shared__ float Ws[CIN*HH]; // 32 KB
    for (int j = threadIdx.x; j < CIN*HH; j += blockDim.x) Ws[j] = W1[j];
    __syncthreads();
    int gw = (blockIdx.x * blockDim.x + threadIdx.x) >> 5;
    int lane = threadIdx.x & 31;
    int nw = (gridDim.x * blockDim.x) >> 5;
    for (int r0 = gw * 4; r0 < Nn; r0 += nw * 4) {
        float a00=0,a01=0,a10=0,a11=0,a20=0,a21=0,a30=0,a31=0;
        const float* x0 = x + (size_t)r0 * CIN;
        #pragma unroll 4
        for (int k = 0; k < CIN; k++) {
            float w0 = Ws[k*HH + lane], w1 = Ws[k*HH + lane + 32];
            float x_0 = __ldg(x0 + k);
            float x_1 = __ldg(x0 + CIN + k);
            float x_2 = __ldg(x0 + 2*CIN + k);
            float x_3 = __ldg(x0 + 3*CIN + k);
            a00 += x_0*w0; a01 += x_0*w1;
            a10 += x_1*w0; a11 += x_1*w1;
            a20 += x_2*w0; a21 += x_2*w1;
            a30 += x_3*w0; a31 += x_3*w1;
        }
        float* o = g_xw + (size_t)r0 * HH;
        o[lane] = a00;        o[lane+32] = a01;
        o[HH+lane] = a10;     o[HH+lane+32] = a11;
        o[2*HH+lane] = a20;   o[2*HH+lane+32] = a21;
        o[3*HH+lane] = a30;   o[3*HH+lane+32] = a31;
    }
}

// ---------------- degree histograms ----------------
__global__ void k_deg(const int* __restrict__ ei, const float* __restrict__ ew, int E) {
    int i = blockIdx.x * blockDim.x + threadIdx.x;
    int stride = gridDim.x * blockDim.x;
    for (int e = i; e < E; e += stride) {
        int c = ei[E + e];                 // edge_index[1]
        atomicAdd(&g_deg[c], ew[e]);
        atomicAdd(&g_degadj[c], 1.0f);
    }
}

__global__ void k_dis() {
    int i = blockIdx.x * blockDim.x + threadIdx.x;
    if (i < Nn) {
        float d = g_deg[i];
        g_dis[i] = d > 0.f ? rsqrtf(d) : 0.f;
    }
}

// ---------------- GCN edge scatter: h[col] += xw[row]*norm ----------------
__global__ __launch_bounds__(256) void k_scatter(const int* __restrict__ ei,
                                                 const float* __restrict__ ew, int E) {
    int gw = (blockIdx.x * blockDim.x + threadIdx.x) >> 5;
    int lane = threadIdx.x & 31;
    int nw = (gridDim.x * blockDim.x) >> 5;
    for (int e = gw; e < E; e += nw) {
        int r = __ldg(ei + e);
        int c = __ldg(ei + E + e);
        float norm = g_dis[r] * __ldg(ew + e) * g_dis[c];
        const float* src = g_xw + (size_t)r * HH;
        float v0 = src[lane] * norm;
        float v1 = src[lane + 32] * norm;
        float* dst = g_hacc + (size_t)c * HH;
        atomicAdd(dst + lane, v0);
        atomicAdd(dst + lane + 32, v1);
    }
}

// ---------------- self-loop + bias + relu ----------------
__global__ void k_h(const float* __restrict__ b1) {
    int i = blockIdx.x * blockDim.x + threadIdx.x;
    int stride = gridDim.x * blockDim.x;
    for (int j = i; j < Nn*HH; j += stride) {
        int r = j >> 6;
        float d = g_dis[r];
        float v = g_hacc[j] + g_xw[j] * d * d + b1[j & 63];
        g_hacc[j] = fmaxf(v, 0.f);
    }
}

// ---------------- fused MLP + softmax + cs/ca stats ----------------
// warp per row; lane owns cols (lane, lane+32)
__global__ __launch_bounds__(256) void k_mlp(const float* __restrict__ Wm1,
                                             const float* __restrict__ bm1,
                                             const float* __restrict__ Wm2,
                                             const float* __restrict__ bm2,
                                             float* __restrict__ out) {
    __shared__ float W1s[HH*HH];  // 16 KB
    __shared__ float W2s[HH*KK];  // 16 KB
    __shared__ float tbuf[8][HH];
    for (int j = threadIdx.x; j < HH*HH; j += blockDim.x) W1s[j] = Wm1[j];
    for (int j = threadIdx.x; j < HH*KK; j += blockDim.x) W2s[j] = Wm2[j];
    __syncthreads();
    int wid = threadIdx.x >> 5;
    int lane = threadIdx.x & 31;
    int gw = blockIdx.x * 8 + wid;
    int nw = gridDim.x * 8;
    int c0 = lane, c1 = lane + 32;
    float b1a = bm1[c0], b1b = bm1[c1];
    float b2a = bm2[c0], b2b = bm2[c1];
    float cs0 = 0.f, cs1 = 0.f, ca0 = 0.f, ca1 = 0.f;
    for (int row = gw; row < Nn; row += nw) {
        const float* hrow = g_hacc + (size_t)row * HH;
        float t0 = b1a, t1 = b1b;
        #pragma unroll 8
        for (int k = 0; k < HH; k++) {
            float hk = __ldg(hrow + k);
            t0 += hk * W1s[k*HH + c0];
            t1 += hk * W1s[k*HH + c1];
        }
        tbuf[wid][c0] = t0; tbuf[wid][c1] = t1;
        __syncwarp();
        float l0 = b2a, l1 = b2b;
        #pragma unroll 8
        for (int k = 0; k < HH; k++) {
            float tk = tbuf[wid][k];
            l0 += tk * W2s[k*KK + c0];
            l1 += tk * W2s[k*KK + c1];
        }
        __syncwarp();
        // softmax over 64 (2 per lane)
        float mx = fmaxf(l0, l1);
        #pragma unroll
        for (int o = 16; o; o >>= 1) mx = fmaxf(mx, __shfl_xor_sync(0xFFFFFFFFu, mx, o));
        float e0 = __expf(l0 - mx), e1 = __expf(l1 - mx);
        float sm = e0 + e1;
        #pragma unroll
        for (int o = 16; o; o >>= 1) sm += __shfl_xor_sync(0xFFFFFFFFu, sm, o);
        float inv = 1.0f / sm;
        float s0 = e0 * inv, s1 = e1 * inv;
        out[(size_t)row*KK + c0] = s0;
        out[(size_t)row*KK + c1] = s1;
        cs0 += s0; cs1 += s1;
        float da = g_degadj[row];
        ca0 += s0 * da; ca1 += s1 * da;
    }
    atomicAdd(&g_cs[c0], cs0); atomicAdd(&g_cs[c1], cs1);
    atomicAdd(&g_ca[c0], ca0); atomicAdd(&g_ca[c1], ca1);
}

// ---------------- ss = s^T s (64x64) ----------------
__global__ __launch_bounds__(256) void k_ss(const float* __restrict__ s) {
    __shared__ float srow[KK];
    int t = threadIdx.x;
    int a = t >> 2;
    int b0 = (t & 3) * 16;
    float acc[16];
    #pragma unroll
    for (int j = 0; j < 16; j++) acc[j] = 0.f;
    for (int row = blockIdx.x; row < Nn; row += gridDim.x) {
        if (t < 16) ((float4*)srow)[t] = ((const float4*)(s + (size_t)row*KK))[t];
        __syncthreads();
        float sa = srow[a];
        #pragma unroll
        for (int j = 0; j < 16; j++) acc[j] += sa * srow[b0 + j];
        __syncthreads();
    }
    #pragma unroll
    for (int j = 0; j < 16; j++) atomicAdd(&g_ss[a*KK + b0 + j], acc[j]);
}

// ---------------- trace(s^T adj s) = sum over edges dot(s[r], s[c]) ----------------
__global__ __launch_bounds__(256) void k_trace(const int* __restrict__ ei,
                                               const float* __restrict__ s, int E) {
    int gw = (blockIdx.x * blockDim.x + threadIdx.x) >> 5;
    int lane = threadIdx.x & 31;
    int nw = (gridDim.x * blockDim.x) >> 5;
    float acc = 0.f;
    for (int e = gw; e < E; e += nw) {
        int r = __ldg(ei + e);
        int c = __ldg(ei + E + e);
        const float* sr = s + (size_t)r * KK;
        const float* sc = s + (size_t)c * KK;
        acc += sr[lane] * sc[lane] + sr[lane + 32] * sc[lane + 32];
    }
    #pragma unroll
    for (int o = 16; o; o >>= 1) acc += __shfl_xor_sync(0xFFFFFFFFu, acc, o);
    if (lane == 0) atomicAdd(&g_trace, (double)acc);
}

// ---------------- final scalar loss ----------------
__global__ __launch_bounds__(256) void k_final(float* __restrict__ out, int E, int out_size) {
    __shared__ float red[256];
    int t = threadIdx.x;

    // sum ca^2
    float v = 0.f;
    for (int i = t; i < KK; i += 256) v += g_ca[i] * g_ca[i];
    red[t] = v; __syncthreads();
    for (int o = 128; o; o >>= 1) { if (t < o) red[t] += red[t + o]; __syncthreads(); }
    float ca2 = red[0]; __syncthreads();

    // sum ss^2 and trace(ss)
    v = 0.f;
    for (int i = t; i < KK*KK; i += 256) v += g_ss[i] * g_ss[i];
    red[t] = v; __syncthreads();
    for (int o = 128; o; o >>= 1) { if (t < o) red[t] += red[t + o]; __syncthreads(); }
    float ss2 = red[0]; __syncthreads();

    v = 0.f;
    for (int i = t; i < KK; i += 256) v += g_ss[i*KK + i];
    red[t] = v; __syncthreads();
    for (int o = 128; o; o >>= 1) { if (t < o) red[t] += red[t + o]; __syncthreads(); }
    float trss = red[0]; __syncthreads();

    // sum cluster_size^2
    v = 0.f;
    for (int i = t; i < KK; i += 256) v += g_cs[i] * g_cs[i];
    red[t] = v; __syncthreads();
    for (int o = 128; o; o >>= 1) { if (t < o) red[t] += red[t + o]; __syncthreads(); }
    float cs2 = red[0]; __syncthreads();

    if (t == 0) {
        float two_m = (float)E;                  // 2m = sum(deg) = E
        float tr_out = (float)g_trace;
        float spectral = -(tr_out - ca2 / two_m) / two_m;
        float ssfro = sqrtf(ss2);
        // ||ss/ssfro - I/8||_F^2 = 1 - trace(ss)/(4*ssfro) + 1
        float ortho = sqrtf(fmaxf(2.0f - trss / (4.0f * ssfro), 0.0f));
        float cluster = sqrtf(cs2) / (float)Nn * 8.0f - 1.0f;
        float loss = spectral + ortho + cluster;
        for (int i = Nn*KK; i < out_size; i++) out[i] = loss;
    }
}

// ---------------- launch ----------------
extern "C" void kernel_launch(void* const* d_in, const int* in_sizes, int n_in,
                              void* d_out, int out_size) {
    const float* x   = (const float*)d_in[0];
    const int*   ei  = (const int*)d_in[1];
    const float* ew  = (const float*)d_in[2];
    const float* W1  = (const float*)d_in[3];
    const float* b1  = (const float*)d_in[4];
    const float* Wm1 = (const float*)d_in[5];
    const float* bm1 = (const float*)d_in[6];
    const float* Wm2 = (const float*)d_in[7];
    const float* bm2 = (const float*)d_in[8];
    float* out = (float*)d_out;
    int E = in_sizes[2];  // edge_weight element count

    k_init<<<1024, 256>>>();
    k_xw<<<512, 256>>>(x, W1);
    k_deg<<<512, 256>>>(ei, ew, E);
    k_dis<<<(Nn + 255) / 256, 256>>>();
    k_scatter<<<2048, 256>>>(ei, ew, E);
    k_h<<<1024, 256>>>(b1);
    k_mlp<<<256, 256>>>(Wm1, bm1, Wm2, bm2, out);
    k_ss<<<256, 256>>>(out);
    k_trace<<<512, 256>>>(ei, out, E);
    k_final<<<1, 256>>>(out, E, out_size);
}